// round 1
// baseline (speedup 1.0000x reference)
#include <cuda_runtime.h>

// Self-attention (N=2, L=2048, H=16, Dv=64) + FC(1024,1024), fp32 baseline.
// Stage 1: flash-style attention per (n, h, 64-query tile) -> g_attn scratch.
// Stage 2: tiled SGEMM  out = g_attn @ fc_w^T + fc_b.

#define L_SEQ   2048
#define D_MODEL 1024
#define N_HEADS 16
#define D_V     64
#define BM      64
#define BN      64
#define PAD     4
#define TSTR    (BM + PAD)   // 68, row stride for transposed smem tiles

// 2*2048*1024 fp32 scratch for attention output (device global: no allocs).
__device__ float g_attn[2 * L_SEQ * D_MODEL];

__global__ __launch_bounds__(256, 2)
void attn_kernel(const float* __restrict__ Q,
                 const float* __restrict__ K,
                 const float* __restrict__ V,
                 const int*   __restrict__ mask)
{
    const int qtile = blockIdx.x;   // 0..31
    const int h     = blockIdx.y;   // 0..15
    const int n     = blockIdx.z;   // 0..1
    const int tid   = threadIdx.x;
    const int tx    = tid & 15;     // output col group (keys / dv)
    const int ty    = tid >> 4;     // output row group (queries)

    __shared__ float Qt[D_V][TSTR];  // [d][r]  (Q tile, transposed)
    __shared__ float Kt[D_V][TSTR];  // [d][c]  (K tile, transposed)
    __shared__ float Vs[BN][TSTR];   // [c][d]  (V tile, natural)
    __shared__ float Pt[BN][TSTR];   // [c][r]  (P tile, transposed)
    __shared__ int   msk[BN];

    const float* qbase = Q + ((size_t)(n * L_SEQ + qtile * BM) * D_MODEL + h * D_V);
    // Load Q tile [64 x 64], store transposed.
    for (int i = tid; i < BM * 16; i += 256) {
        int r  = i >> 4;
        int c4 = (i & 15) << 2;
        float4 v = *(const float4*)(qbase + (size_t)r * D_MODEL + c4);
        Qt[c4 + 0][r] = v.x; Qt[c4 + 1][r] = v.y;
        Qt[c4 + 2][r] = v.z; Qt[c4 + 3][r] = v.w;
    }

    float acc[4][4];
    #pragma unroll
    for (int i = 0; i < 4; i++)
        #pragma unroll
        for (int j = 0; j < 4; j++) acc[i][j] = 0.f;
    float mrow[4], lrow[4];
    #pragma unroll
    for (int i = 0; i < 4; i++) { mrow[i] = -1e30f; lrow[i] = 0.f; }

    const float* kbase = K + ((size_t)n * L_SEQ * D_MODEL + h * D_V);
    const float* vbase = V + ((size_t)n * L_SEQ * D_MODEL + h * D_V);
    const int*   mbase = mask + n * L_SEQ;

    for (int kb = 0; kb < L_SEQ / BN; kb++) {
        __syncthreads();   // prior-iter readers of Kt/Vs/Pt are done
        const float* kp = kbase + (size_t)kb * BN * D_MODEL;
        const float* vp = vbase + (size_t)kb * BN * D_MODEL;
        for (int i = tid; i < BN * 16; i += 256) {
            int r  = i >> 4;
            int c4 = (i & 15) << 2;
            float4 kv = *(const float4*)(kp + (size_t)r * D_MODEL + c4);
            Kt[c4 + 0][r] = kv.x; Kt[c4 + 1][r] = kv.y;
            Kt[c4 + 2][r] = kv.z; Kt[c4 + 3][r] = kv.w;
            float4 vv = *(const float4*)(vp + (size_t)r * D_MODEL + c4);
            *(float4*)&Vs[r][c4] = vv;
        }
        if (tid < BN) msk[tid] = mbase[kb * BN + tid];
        __syncthreads();

        // S = (Q K^T) / 32, with key-padding mask -> -1e30 (finite sentinel).
        float s[4][4];
        #pragma unroll
        for (int i = 0; i < 4; i++)
            #pragma unroll
            for (int j = 0; j < 4; j++) s[i][j] = 0.f;
        #pragma unroll 8
        for (int kk = 0; kk < D_V; kk++) {
            float4 qv = *(const float4*)&Qt[kk][4 * ty];
            float4 kv = *(const float4*)&Kt[kk][4 * tx];
            float qa[4] = {qv.x, qv.y, qv.z, qv.w};
            float ka[4] = {kv.x, kv.y, kv.z, kv.w};
            #pragma unroll
            for (int i = 0; i < 4; i++)
                #pragma unroll
                for (int j = 0; j < 4; j++) s[i][j] += qa[i] * ka[j];
        }
        int mk[4];
        #pragma unroll
        for (int j = 0; j < 4; j++) mk[j] = msk[4 * tx + j];
        #pragma unroll
        for (int i = 0; i < 4; i++)
            #pragma unroll
            for (int j = 0; j < 4; j++)
                s[i][j] = mk[j] ? s[i][j] * 0.03125f : -1e30f;

        // Online softmax: per-row max/sum reduced across the 16-lane tx group.
        float mnew[4], alpha[4];
        #pragma unroll
        for (int i = 0; i < 4; i++) {
            float v = fmaxf(fmaxf(s[i][0], s[i][1]), fmaxf(s[i][2], s[i][3]));
            #pragma unroll
            for (int off = 8; off >= 1; off >>= 1)
                v = fmaxf(v, __shfl_xor_sync(0xffffffffu, v, off));
            mnew[i]  = fmaxf(mrow[i], v);
            alpha[i] = __expf(mrow[i] - mnew[i]);
        }
        #pragma unroll
        for (int i = 0; i < 4; i++) {
            float sum = 0.f;
            #pragma unroll
            for (int j = 0; j < 4; j++) {
                float p = __expf(s[i][j] - mnew[i]);
                s[i][j] = p;
                sum += p;
            }
            #pragma unroll
            for (int off = 8; off >= 1; off >>= 1)
                sum += __shfl_xor_sync(0xffffffffu, sum, off);
            lrow[i] = lrow[i] * alpha[i] + sum;
            mrow[i] = mnew[i];
        }
        #pragma unroll
        for (int i = 0; i < 4; i++)
            #pragma unroll
            for (int j = 0; j < 4; j++) acc[i][j] *= alpha[i];

        // Stage P transposed, then O += P @ V.
        #pragma unroll
        for (int j = 0; j < 4; j++)
            *(float4*)&Pt[4 * tx + j][4 * ty] =
                make_float4(s[0][j], s[1][j], s[2][j], s[3][j]);
        __syncthreads();
        #pragma unroll 8
        for (int c = 0; c < BN; c++) {
            float4 pv = *(const float4*)&Pt[c][4 * ty];
            float4 vv = *(const float4*)&Vs[c][4 * tx];
            float pa[4] = {pv.x, pv.y, pv.z, pv.w};
            float va[4] = {vv.x, vv.y, vv.z, vv.w};
            #pragma unroll
            for (int i = 0; i < 4; i++)
                #pragma unroll
                for (int j = 0; j < 4; j++) acc[i][j] += pa[i] * va[j];
        }
    }

    // Epilogue: normalize and store to scratch (layout [n, q, h*64 + d]).
    float* obase = g_attn + ((size_t)(n * L_SEQ + qtile * BM) * D_MODEL + h * D_V);
    #pragma unroll
    for (int i = 0; i < 4; i++) {
        float inv = 1.f / lrow[i];
        float4 o = make_float4(acc[i][0] * inv, acc[i][1] * inv,
                               acc[i][2] * inv, acc[i][3] * inv);
        *(float4*)(obase + (size_t)(4 * ty + i) * D_MODEL + 4 * tx) = o;
    }
}

// out[m][o] = sum_k X[m][k] * W[o][k] + b[o];  X = g_attn, M = 4096.
__global__ __launch_bounds__(256, 2)
void fc_kernel(const float* __restrict__ W,
               const float* __restrict__ b,
               float*       __restrict__ out)
{
    const int otile = blockIdx.x;   // 0..15
    const int mtile = blockIdx.y;   // 0..63
    const int tid = threadIdx.x;
    const int tx = tid & 15, ty = tid >> 4;

    __shared__ float Xt[64][TSTR];  // [k][m]
    __shared__ float Wt[64][TSTR];  // [k][o]

    float acc[4][4];
    #pragma unroll
    for (int i = 0; i < 4; i++)
        #pragma unroll
        for (int j = 0; j < 4; j++) acc[i][j] = 0.f;

    for (int kb = 0; kb < D_MODEL / 64; kb++) {
        __syncthreads();
        for (int i = tid; i < 64 * 16; i += 256) {
            int r  = i >> 4;
            int c4 = (i & 15) << 2;
            float4 xv = *(const float4*)(g_attn +
                (size_t)(mtile * 64 + r) * D_MODEL + kb * 64 + c4);
            Xt[c4 + 0][r] = xv.x; Xt[c4 + 1][r] = xv.y;
            Xt[c4 + 2][r] = xv.z; Xt[c4 + 3][r] = xv.w;
            float4 wv = *(const float4*)(W +
                (size_t)(otile * 64 + r) * D_MODEL + kb * 64 + c4);
            Wt[c4 + 0][r] = wv.x; Wt[c4 + 1][r] = wv.y;
            Wt[c4 + 2][r] = wv.z; Wt[c4 + 3][r] = wv.w;
        }
        __syncthreads();
        #pragma unroll 8
        for (int kk = 0; kk < 64; kk++) {
            float4 xv = *(const float4*)&Xt[kk][4 * ty];
            float4 wv = *(const float4*)&Wt[kk][4 * tx];
            float xa[4] = {xv.x, xv.y, xv.z, xv.w};
            float wa[4] = {wv.x, wv.y, wv.z, wv.w};
            #pragma unroll
            for (int i = 0; i < 4; i++)
                #pragma unroll
                for (int j = 0; j < 4; j++) acc[i][j] += xa[i] * wa[j];
        }
    }

    float bj[4];
    #pragma unroll
    for (int j = 0; j < 4; j++) bj[j] = b[otile * 64 + 4 * tx + j];
    #pragma unroll
    for (int i = 0; i < 4; i++) {
        float4 o = make_float4(acc[i][0] + bj[0], acc[i][1] + bj[1],
                               acc[i][2] + bj[2], acc[i][3] + bj[3]);
        *(float4*)(out + (size_t)(mtile * 64 + 4 * ty + i) * D_MODEL
                       + otile * 64 + 4 * tx) = o;
    }
}

extern "C" void kernel_launch(void* const* d_in, const int* in_sizes, int n_in,
                              void* d_out, int out_size)
{
    const float* q    = (const float*)d_in[0];
    const float* k    = (const float*)d_in[1];
    const float* v    = (const float*)d_in[2];
    const int*   mask = (const int*)  d_in[3];
    const float* fw   = (const float*)d_in[4];
    const float* fb   = (const float*)d_in[5];
    float* out = (float*)d_out;

    dim3 g1(L_SEQ / BM, N_HEADS, 2);
    attn_kernel<<<g1, 256>>>(q, k, v, mask);

    dim3 g2(D_MODEL / 64, (2 * L_SEQ) / 64);
    fc_kernel<<<g2, 256>>>(fw, fb, out);
}